// round 1
// baseline (speedup 1.0000x reference)
#include <cuda_runtime.h>
#include <cuda_bf16.h>

// Cutout: out = x with a 16x16 box (centered at (cy[b], cx[b])) zeroed, per image.
// x: [B=256, C=3, H=224, W=224] fp32, contiguous. cy, cx: [1, 256] int32.
// Pure streaming masked copy -> float4 vectorized, one float4 per thread.

#define B 256
#define C 3
#define H 224
#define W 224
#define HALF 8

// float4 counts (all divisible cleanly since W % 4 == 0)
#define W4     (W / 4)          // 56
#define HW4    (H * W4)         // 12544
#define CHW4   (C * HW4)        // 37632
#define TOTAL4 (B * CHW4)       // 9,633,792

__global__ void __launch_bounds__(256) cutout_kernel(
    const float4* __restrict__ x,
    const int*    __restrict__ cy,
    const int*    __restrict__ cx,
    float4*       __restrict__ out)
{
    int i = blockIdx.x * blockDim.x + threadIdx.x;
    if (i >= TOTAL4) return;

    // Decompose: i -> (b, c, h, w4). Divisions by compile-time constants
    // lower to IMAD magic-multiply sequences.
    int b    = i / CHW4;
    int rem  = i - b * CHW4;
    int hw4  = rem % HW4;          // position within the HxW plane (c irrelevant to mask)
    int h    = hw4 / W4;
    int w    = (hw4 - h * W4) * 4; // first of 4 consecutive W-coords

    float4 v = x[i];

    int yc = __ldg(&cy[b]);
    int xc = __ldg(&cx[b]);

    // Inside-row check first; per-lane column check.
    if (h >= yc - HALF && h < yc + HALF) {
        int x0 = xc - HALF, x1 = xc + HALF;
        if (w + 0 >= x0 && w + 0 < x1) v.x = 0.0f;
        if (w + 1 >= x0 && w + 1 < x1) v.y = 0.0f;
        if (w + 2 >= x0 && w + 2 < x1) v.z = 0.0f;
        if (w + 3 >= x0 && w + 3 < x1) v.w = 0.0f;
    }

    out[i] = v;
}

extern "C" void kernel_launch(void* const* d_in, const int* in_sizes, int n_in,
                              void* d_out, int out_size)
{
    const float4* x  = (const float4*)d_in[0];
    const int*    cy = (const int*)   d_in[1];
    const int*    cx = (const int*)   d_in[2];
    float4*       out = (float4*)d_out;

    const int threads = 256;
    const int blocks  = (TOTAL4 + threads - 1) / threads;  // 37632
    cutout_kernel<<<blocks, threads>>>(x, cy, cx, out);
}

// round 2
// speedup vs baseline: 1.0184x; 1.0184x over previous
#include <cuda_runtime.h>
#include <cuda_bf16.h>

// Cutout: out = x with a 16x16 box (centered at (cy[b], cx[b])) zeroed, per image.
// x: [B=256, C=3, H=224, W=224] fp32, contiguous. cy, cx: [1, 256] int32.
// Streaming masked copy, float4-vectorized, 4 float4 per thread with
// front-batched loads (MLP=4). Unroll stride = 64 full images, so the
// (h, w) decomposition is computed ONCE per thread; only b changes.

#define B 256
#define C 3
#define H 224
#define W 224
#define HALF 8

#define W4     (W / 4)          // 56
#define HW4    (H * W4)         // 12544
#define CHW4   (C * HW4)        // 37632
#define TOTAL4 (B * CHW4)       // 9,633,792
#define UNROLL 4
#define CHUNK  (TOTAL4 / UNROLL) // 2,408,448 == 64 * CHW4  (b advances by 64)

__global__ void __launch_bounds__(256) cutout_kernel(
    const float4* __restrict__ x,
    const int*    __restrict__ cy,
    const int*    __restrict__ cx,
    float4*       __restrict__ out)
{
    int i = blockIdx.x * blockDim.x + threadIdx.x;
    if (i >= CHUNK) return;

    // Decompose once: i -> (b0, h, w). Sub-elements j share (c,h,w); b_j = b0 + 64*j.
    int b0   = i / CHW4;              // 0..63
    int rem  = i - b0 * CHW4;
    int hw4  = rem % HW4;
    int h    = hw4 / W4;
    int w    = (hw4 - h * W4) * 4;    // first of 4 consecutive W-coords

    // Front-batch all 4 independent 128-bit loads (MLP=4).
    float4 v0 = x[i + 0 * CHUNK];
    float4 v1 = x[i + 1 * CHUNK];
    float4 v2 = x[i + 2 * CHUNK];
    float4 v3 = x[i + 3 * CHUNK];

    // Hole centers for the 4 images (small, L1/L2-resident broadcasts).
    int yc0 = __ldg(&cy[b0 +   0]), xc0 = __ldg(&cx[b0 +   0]);
    int yc1 = __ldg(&cy[b0 +  64]), xc1 = __ldg(&cx[b0 +  64]);
    int yc2 = __ldg(&cy[b0 + 128]), xc2 = __ldg(&cx[b0 + 128]);
    int yc3 = __ldg(&cy[b0 + 192]), xc3 = __ldg(&cx[b0 + 192]);

    #define APPLY(v, yc, xc)                                   \
        if (h >= (yc) - HALF && h < (yc) + HALF) {             \
            int x0 = (xc) - HALF, x1 = (xc) + HALF;            \
            if (w + 0 >= x0 && w + 0 < x1) (v).x = 0.0f;       \
            if (w + 1 >= x0 && w + 1 < x1) (v).y = 0.0f;       \
            if (w + 2 >= x0 && w + 2 < x1) (v).z = 0.0f;       \
            if (w + 3 >= x0 && w + 3 < x1) (v).w = 0.0f;       \
        }

    APPLY(v0, yc0, xc0);
    APPLY(v1, yc1, xc1);
    APPLY(v2, yc2, xc2);
    APPLY(v3, yc3, xc3);

    out[i + 0 * CHUNK] = v0;
    out[i + 1 * CHUNK] = v1;
    out[i + 2 * CHUNK] = v2;
    out[i + 3 * CHUNK] = v3;
}

extern "C" void kernel_launch(void* const* d_in, const int* in_sizes, int n_in,
                              void* d_out, int out_size)
{
    const float4* x   = (const float4*)d_in[0];
    const int*    cy  = (const int*)   d_in[1];
    const int*    cx  = (const int*)   d_in[2];
    float4*       out = (float4*)d_out;

    const int threads = 256;
    const int blocks  = (CHUNK + threads - 1) / threads;  // 9408
    cutout_kernel<<<blocks, threads>>>(x, cy, cx, out);
}